// round 15
// baseline (speedup 1.0000x reference)
#include <cuda_runtime.h>
#include <math_constants.h>

// Scratch + sync (no device allocs allowed)
__device__ float g_map[32 * 2 * 64 * 64];   // [b][2][4096]
__device__ float g_scale[32 * 64 * 64];     // [b][4096]
__device__ unsigned int g_k1done[32];       // K1 blocks done per image (target 32)

#define NB 32
#define NC 256
#define HW 4096
#define HW4 1024

__global__ void init_kernel() {
    if (threadIdx.x < 32) g_k1done[threadIdx.x] = 0;
}

// ---- fused K1+K2 block: channel max+mean for 32 float4 pixels; the LAST
// block to finish an image computes that image's 7x7 conv + sigmoid inline
// (threadfence-reduction pattern; no spin blocks anywhere). ----
__device__ __forceinline__ void k1k2_body(const float* __restrict__ x,
                                          const float* __restrict__ w,
                                          int local, int b0) {
    __shared__ float4 smax[8][32];
    __shared__ float4 ssum[8][32];
    __shared__ unsigned int s_last;

    int lane = threadIdx.x & 31;
    int wrp  = threadIdx.x >> 5;
    int b    = b0 + (local >> 5);
    int p4   = ((local & 31) << 5) + lane;

    const float4* __restrict__ xv = reinterpret_cast<const float4*>(x);
    size_t base = (size_t)b * (NC * HW4) + (size_t)(wrp << 5) * HW4 + p4;

    float4 mx = make_float4(-CUDART_INF_F, -CUDART_INF_F, -CUDART_INF_F, -CUDART_INF_F);
    float4 sm = make_float4(0.f, 0.f, 0.f, 0.f);
    #pragma unroll
    for (int c = 0; c < 32; c++) {
        float4 v = __ldg(&xv[base + (size_t)c * HW4]);
        mx.x = fmaxf(mx.x, v.x); mx.y = fmaxf(mx.y, v.y);
        mx.z = fmaxf(mx.z, v.z); mx.w = fmaxf(mx.w, v.w);
        sm.x += v.x; sm.y += v.y; sm.z += v.z; sm.w += v.w;
    }
    smax[wrp][lane] = mx;
    ssum[wrp][lane] = sm;
    __syncthreads();

    if (wrp == 0) {
        float4 m = smax[0][lane];
        float4 s = ssum[0][lane];
        #pragma unroll
        for (int ww = 1; ww < 8; ww++) {
            float4 m2 = smax[ww][lane];
            float4 s2 = ssum[ww][lane];
            m.x = fmaxf(m.x, m2.x); m.y = fmaxf(m.y, m2.y);
            m.z = fmaxf(m.z, m2.z); m.w = fmaxf(m.w, m2.w);
            s.x += s2.x; s.y += s2.y; s.z += s2.z; s.w += s2.w;
        }
        const float inv = 1.0f / (float)NC;
        s.x *= inv; s.y *= inv; s.z *= inv; s.w *= inv;
        float4* mv = reinterpret_cast<float4*>(g_map);
        mv[(size_t)b * 2048 + p4]        = m;
        mv[(size_t)b * 2048 + 1024 + p4] = s;
        __threadfence();   // release: every warp-0 lane fences its own stores
    }
    __syncthreads();
    if (threadIdx.x == 0)
        s_last = (atomicAdd(&g_k1done[b], 1u) == 31u) ? 1u : 0u;
    __syncthreads();

    if (s_last) {
        // ---- K2 for whole image b: 4096 pixels / 256 threads = 16 each ----
        __shared__ float sw[98];
        if (threadIdx.x < 98) sw[threadIdx.x] = __ldg(&w[threadIdx.x]);
        __threadfence();   // acquire side (paired with writers' release)
        __syncthreads();

        const float* __restrict__ mp = g_map + (size_t)b * 2 * HW;
        float* __restrict__ sc = g_scale + (size_t)b * HW;

        #pragma unroll
        for (int it = 0; it < 16; it++) {
            int hw = it * 256 + threadIdx.x;
            int h  = hw >> 6;
            int wc = hw & 63;
            float acc = 0.f;
            #pragma unroll
            for (int ky = 0; ky < 7; ky++) {
                int hy = h + ky - 3;
                if (hy < 0 || hy >= 64) continue;
                #pragma unroll
                for (int kx = 0; kx < 7; kx++) {
                    int wx = wc + kx - 3;
                    if (wx < 0 || wx >= 64) continue;
                    int q = hy * 64 + wx;
                    acc = fmaf(sw[ky * 7 + kx],      mp[q],      acc);
                    acc = fmaf(sw[49 + ky * 7 + kx], mp[HW + q], acc);
                }
            }
            sc[hw] = 1.0f / (1.0f + __expf(-acc));
        }
    }
}

// ---- K3 body: one channel plane (1024 float4) of out = x*scale; no deps ----
__device__ __forceinline__ void k3_body(const float* __restrict__ x,
                                        float* __restrict__ out, size_t plane) {
    const float4* __restrict__ xv = reinterpret_cast<const float4*>(x);
    const float4* __restrict__ sv = reinterpret_cast<const float4*>(g_scale);
    float4* __restrict__ ov = reinterpret_cast<float4*>(out);

    size_t blk = plane << 10;
    int b = (int)(plane >> 8);

    float4 v[4], s[4];
    #pragma unroll
    for (int k = 0; k < 4; k++) {
        size_t i = blk + k * 256 + threadIdx.x;
        v[k] = __ldcs(&xv[i]);
        s[k] = __ldg(&sv[(size_t)b * HW4 + (i & 1023)]);
    }
    #pragma unroll
    for (int k = 0; k < 4; k++) {
        size_t i = blk + k * 256 + threadIdx.x;
        v[k].x *= s[k].x; v[k].y *= s[k].y; v[k].z *= s[k].z; v[k].w *= s[k].w;
        __stcs(&ov[i], v[k]);
    }
}

// ---- L1: K1K2(h0), 512 blocks ----
__global__ __launch_bounds__(256) void phaseA_kernel(const float* __restrict__ x,
                                                     const float* __restrict__ w) {
    k1k2_body(x, w, blockIdx.x, 0);
}

// ---- L2: K1K2(h1) || K3(h0), 4608 blocks, no internal deps/spins ----
__global__ __launch_bounds__(256) void phaseB_kernel(const float* __restrict__ x,
                                                     const float* __restrict__ w,
                                                     float* __restrict__ out) {
    int bid = blockIdx.x;
    if (bid < 512) k1k2_body(x, w, bid, 16);
    else           k3_body(x, out, (size_t)(bid - 512));
}

// ---- L3: K3(h1), 4096 blocks ----
__global__ __launch_bounds__(256) void phaseC_kernel(const float* __restrict__ x,
                                                     float* __restrict__ out) {
    k3_body(x, out, (size_t)blockIdx.x + 4096);
}

extern "C" void kernel_launch(void* const* d_in, const int* in_sizes, int n_in,
                              void* d_out, int out_size) {
    const float* x = (const float*)d_in[0];
    const float* w = (const float*)d_in[1];
    float* out = (float*)d_out;

    init_kernel<<<1, 32>>>();
    phaseA_kernel<<<512, 256>>>(x, w);
    phaseB_kernel<<<4608, 256>>>(x, w, out);
    phaseC_kernel<<<4096, 256>>>(x, out);
}

// round 17
// speedup vs baseline: 2.1995x; 2.1995x over previous
#include <cuda_runtime.h>
#include <math_constants.h>

// Scratch (no device allocs allowed). No sync state: all cross-stage
// dependencies are enforced by launch boundaries only.
__device__ float g_map[32 * 2 * 64 * 64];   // [b][2][4096]
__device__ float g_scale[32 * 64 * 64];     // [b][4096]

#define NB 32
#define NC 256
#define HW 4096
#define HW4 1024

#define CHUNK 8                 // images per chunk
#define K1_PER_CHUNK 256        // 32 blocks per image
#define K2_PER_CHUNK 128        // 16 blocks per image (256 px each)
#define K3_PER_CHUNK 2048       // 256 planes per image

// ---- K1 body: channel max+mean for 32 float4 pixels ----
__device__ __forceinline__ void k1_body(const float* __restrict__ x, int local, int b0) {
    __shared__ float4 smax[8][32];
    __shared__ float4 ssum[8][32];

    int lane = threadIdx.x & 31;
    int wrp  = threadIdx.x >> 5;
    int b    = b0 + (local >> 5);
    int p4   = ((local & 31) << 5) + lane;

    const float4* __restrict__ xv = reinterpret_cast<const float4*>(x);
    size_t base = (size_t)b * (NC * HW4) + (size_t)(wrp << 5) * HW4 + p4;

    float4 mx = make_float4(-CUDART_INF_F, -CUDART_INF_F, -CUDART_INF_F, -CUDART_INF_F);
    float4 sm = make_float4(0.f, 0.f, 0.f, 0.f);
    #pragma unroll
    for (int c = 0; c < 32; c++) {
        float4 v = __ldg(&xv[base + (size_t)c * HW4]);
        mx.x = fmaxf(mx.x, v.x); mx.y = fmaxf(mx.y, v.y);
        mx.z = fmaxf(mx.z, v.z); mx.w = fmaxf(mx.w, v.w);
        sm.x += v.x; sm.y += v.y; sm.z += v.z; sm.w += v.w;
    }
    smax[wrp][lane] = mx;
    ssum[wrp][lane] = sm;
    __syncthreads();

    if (wrp == 0) {
        float4 m = smax[0][lane];
        float4 s = ssum[0][lane];
        #pragma unroll
        for (int w = 1; w < 8; w++) {
            float4 m2 = smax[w][lane];
            float4 s2 = ssum[w][lane];
            m.x = fmaxf(m.x, m2.x); m.y = fmaxf(m.y, m2.y);
            m.z = fmaxf(m.z, m2.z); m.w = fmaxf(m.w, m2.w);
            s.x += s2.x; s.y += s2.y; s.z += s2.z; s.w += s2.w;
        }
        const float inv = 1.0f / (float)NC;
        s.x *= inv; s.y *= inv; s.z *= inv; s.w *= inv;
        float4* mv = reinterpret_cast<float4*>(g_map);
        mv[(size_t)b * 2048 + p4]        = m;
        mv[(size_t)b * 2048 + 1024 + p4] = s;
    }
}

// ---- K2 body: conv7x7+sigmoid for 256 pixels (no deps inside launch) ----
__device__ __forceinline__ void k2_body(const float* __restrict__ w, int local, int b0) {
    __shared__ float sw[98];
    if (threadIdx.x < 98) sw[threadIdx.x] = __ldg(&w[threadIdx.x]);
    __syncthreads();

    int b  = b0 + (local >> 4);
    int hw = ((local & 15) << 8) + threadIdx.x;
    int h  = hw >> 6;
    int wc = hw & 63;
    const float* __restrict__ mp = g_map + (size_t)b * 2 * HW;

    float acc = 0.f;
    #pragma unroll
    for (int ky = 0; ky < 7; ky++) {
        int hy = h + ky - 3;
        if (hy < 0 || hy >= 64) continue;
        #pragma unroll
        for (int kx = 0; kx < 7; kx++) {
            int wx = wc + kx - 3;
            if (wx < 0 || wx >= 64) continue;
            int q = hy * 64 + wx;
            acc = fmaf(sw[ky * 7 + kx],      __ldg(&mp[q]),      acc);
            acc = fmaf(sw[49 + ky * 7 + kx], __ldg(&mp[HW + q]), acc);
        }
    }
    g_scale[(size_t)b * HW + hw] = 1.0f / (1.0f + __expf(-acc));
}

// ---- K3 body: one channel plane (1024 float4) of out = x*scale ----
__device__ __forceinline__ void k3_body(const float* __restrict__ x,
                                        float* __restrict__ out, size_t plane) {
    const float4* __restrict__ xv = reinterpret_cast<const float4*>(x);
    const float4* __restrict__ sv = reinterpret_cast<const float4*>(g_scale);
    float4* __restrict__ ov = reinterpret_cast<float4*>(out);

    size_t blk = plane << 10;
    int b = (int)(plane >> 8);

    float4 v[4], s[4];
    #pragma unroll
    for (int k = 0; k < 4; k++) {
        size_t i = blk + k * 256 + threadIdx.x;
        v[k] = __ldcs(&xv[i]);
        s[k] = __ldg(&sv[(size_t)b * HW4 + (i & 1023)]);
    }
    #pragma unroll
    for (int k = 0; k < 4; k++) {
        size_t i = blk + k * 256 + threadIdx.x;
        v[k].x *= s[k].x; v[k].y *= s[k].y; v[k].z *= s[k].z; v[k].w *= s[k].w;
        __stcs(&ov[i], v[k]);
    }
}

// ---- generic phase kernel: [0,n1)=K1(chunk c1), [n1,n1+n2)=K2(chunk c2),
//      rest = K3(chunk c3). Stages inside one launch are independent. ----
__global__ __launch_bounds__(256) void phase_kernel(const float* __restrict__ x,
                                                    const float* __restrict__ w,
                                                    float* __restrict__ out,
                                                    int n1, int c1,
                                                    int n2, int c2,
                                                    int c3) {
    int bid = blockIdx.x;
    if (bid < n1) {
        k1_body(x, bid, c1 * CHUNK);
    } else if (bid < n1 + n2) {
        k2_body(w, bid - n1, c2 * CHUNK);
    } else {
        k3_body(x, out, (size_t)c3 * K3_PER_CHUNK + (bid - n1 - n2));
    }
}

extern "C" void kernel_launch(void* const* d_in, const int* in_sizes, int n_in,
                              void* d_out, int out_size) {
    const float* x = (const float*)d_in[0];
    const float* w = (const float*)d_in[1];
    float* out = (float*)d_out;

    const int K1 = K1_PER_CHUNK, K2 = K2_PER_CHUNK, K3 = K3_PER_CHUNK;

    // P0: K1(c0)
    phase_kernel<<<K1, 256>>>(x, w, out, K1, 0, 0, 0, 0);
    // P1: K1(c1) + K2(c0)
    phase_kernel<<<K1 + K2, 256>>>(x, w, out, K1, 1, K2, 0, 0);
    // P2: K1(c2) + K2(c1) + K3(c0)
    phase_kernel<<<K1 + K2 + K3, 256>>>(x, w, out, K1, 2, K2, 1, 0);
    // P3: K1(c3) + K2(c2) + K3(c1)
    phase_kernel<<<K1 + K2 + K3, 256>>>(x, w, out, K1, 3, K2, 2, 1);
    // P4: K2(c3) + K3(c2)
    phase_kernel<<<K2 + K3, 256>>>(x, w, out, 0, 0, K2, 3, 2);
    // P5: K3(c3)
    phase_kernel<<<K3, 256>>>(x, w, out, 0, 0, 0, 0, 3);
}